// round 3
// baseline (speedup 1.0000x reference)
#include <cuda_runtime.h>
#include <math.h>

// Problem constants (fixed by the reference)
#define POOL   100
#define NTASKS 10
#define NB_PT  (POOL / NTASKS)       // 10
#define PLEN   8
#define EMBD   768
#define BATCH  512
#define ED4    (EMBD / 4)            // 192

#define BPB         4                // batch rows per pmt block
#define PMT_BLOCKS  (BATCH / BPB)    // 128
#define COPY_BLOCKS 2560
#define OUT_PER_T   ((PLEN * ED4) / 256)   // 6 float4 outputs per thread

// ---------------------------------------------------------------------------
// Single mega kernel:
//   blocks [0, PMT_BLOCKS): self-contained diag+sim+einsum for 4 batch rows.
//   blocks [PMT_BLOCKS, ...): streaming copy x_block -> out tail.
// ---------------------------------------------------------------------------
__global__ void __launch_bounds__(256) mega_kernel(
        const float* __restrict__ x_querry,
        const float* __restrict__ e_a,
        const float* __restrict__ e_p,
        const float* __restrict__ x_block,
        const int*   __restrict__ task_id_p,
        float* __restrict__ out,
        size_t xb_float4s) {
    if (blockIdx.x >= PMT_BLOCKS) {
        // ================= streaming copy =================
        const float4* src = (const float4*)x_block;
        float4* dst = (float4*)(out + (size_t)BATCH * PLEN * EMBD);

        const size_t stride = (size_t)COPY_BLOCKS * 256;
        size_t i = (size_t)(blockIdx.x - PMT_BLOCKS) * 256 + threadIdx.x;

        // 8-way independent unroll for MLP
        for (; i + 7 * stride < xb_float4s; i += 8 * stride) {
            float4 v0 = __ldcs(src + i);
            float4 v1 = __ldcs(src + i + stride);
            float4 v2 = __ldcs(src + i + 2 * stride);
            float4 v3 = __ldcs(src + i + 3 * stride);
            float4 v4 = __ldcs(src + i + 4 * stride);
            float4 v5 = __ldcs(src + i + 5 * stride);
            float4 v6 = __ldcs(src + i + 6 * stride);
            float4 v7 = __ldcs(src + i + 7 * stride);
            __stcs(dst + i,              v0);
            __stcs(dst + i + stride,     v1);
            __stcs(dst + i + 2 * stride, v2);
            __stcs(dst + i + 3 * stride, v3);
            __stcs(dst + i + 4 * stride, v4);
            __stcs(dst + i + 5 * stride, v5);
            __stcs(dst + i + 6 * stride, v6);
            __stcs(dst + i + 7 * stride, v7);
        }
        for (; i < xb_float4s; i += stride)
            __stcs(dst + i, __ldcs(src + i));
        return;
    }

    // ================= pmt path (diag + sim + einsum) =================
    const int task_end = (*task_id_p + 1) * NB_PT;
    const int b0 = blockIdx.x * BPB;
    const int tid = threadIdx.x;
    const int warp = tid >> 5;
    const int lane = tid & 31;

    __shared__ float s_diag[NB_PT * EMBD];   // 30 KB
    __shared__ float s_sim[BPB][NB_PT];

    float4 acc[BPB][OUT_PER_T];
#pragma unroll
    for (int bs = 0; bs < BPB; bs++)
#pragma unroll
        for (int j = 0; j < OUT_PER_T; j++)
            acc[bs][j] = make_float4(0.f, 0.f, 0.f, 0.f);

    const float4* ep4 = (const float4*)e_p;

    for (int kc = 0; kc < task_end; kc += NB_PT) {
        const int kn = min(NB_PT, task_end - kc);
        __syncthreads();   // protect s_diag/s_sim reuse across chunks

        // ---- phase A: diag[kk][d] = sum_l e_p[kc+kk, l, d]^2 ----
        for (int i = tid; i < kn * ED4; i += 256) {
            int kk = i / ED4;
            int d4 = i % ED4;
            const float4* p = ep4 + ((size_t)(kc + kk) * PLEN) * ED4 + d4;
            float4 a = make_float4(0.f, 0.f, 0.f, 0.f);
#pragma unroll
            for (int l = 0; l < PLEN; l++) {
                float4 v = p[l * ED4];
                a.x += v.x * v.x; a.y += v.y * v.y;
                a.z += v.z * v.z; a.w += v.w * v.w;
            }
            ((float4*)s_diag)[kk * ED4 + d4] = a;
        }
        __syncthreads();

        // ---- phase B: sims for (bs, kk), distributed over 8 warps ----
        for (int t = warp; t < BPB * kn; t += 8) {
            int bs = t / kn;
            int kk = t % kn;
            int k = kc + kk;
            int row = POOL - task_end + k;

            const float4* xq4 = (const float4*)(x_querry +
                                ((size_t)(b0 + bs) * POOL + row) * EMBD);
            const float4* ea4 = (const float4*)(e_a + (size_t)k * EMBD);
            const float4* dg4 = (const float4*)(s_diag + kk * EMBD);

            float s1 = 0.f, s2 = 0.f, s3 = 0.f;
#pragma unroll
            for (int j = 0; j < ED4 / 32; j++) {   // 6 iterations
                int idx = lane + j * 32;
                float4 x = xq4[idx];
                float4 e = ea4[idx];
                float4 g = dg4[idx];
                float a, aa;
                a = x.x * e.x; aa = a * a; s3 += aa; s1 += aa * g.x; s2 += aa * g.x * g.x;
                a = x.y * e.y; aa = a * a; s3 += aa; s1 += aa * g.y; s2 += aa * g.y * g.y;
                a = x.z * e.z; aa = a * a; s3 += aa; s1 += aa * g.z; s2 += aa * g.z * g.z;
                a = x.w * e.w; aa = a * a; s3 += aa; s1 += aa * g.w; s2 += aa * g.w * g.w;
            }
#pragma unroll
            for (int o = 16; o > 0; o >>= 1) {
                s1 += __shfl_down_sync(0xFFFFFFFFu, s1, o);
                s2 += __shfl_down_sync(0xFFFFFFFFu, s2, o);
                s3 += __shfl_down_sync(0xFFFFFFFFu, s3, o);
            }
            if (lane == 0) {
                const float eps = 1e-12f;
                float n1 = fmaxf(sqrtf(s2), eps);
                float n2 = fmaxf(sqrtf(s3), eps);
                s_sim[bs][kk] = s1 / (n1 * n2);
            }
        }
        __syncthreads();

        // ---- phase C: accumulate einsum; each e_p float4 feeds 4 batches ----
        for (int kk = 0; kk < kn; kk++) {
            float sv[BPB];
#pragma unroll
            for (int bs = 0; bs < BPB; bs++) sv[bs] = s_sim[bs][kk];
#pragma unroll
            for (int j = 0; j < OUT_PER_T; j++) {
                int idx = tid + j * 256;
                int l  = idx / ED4;
                int d4 = idx % ED4;
                float4 v = ep4[((size_t)(kc + kk) * PLEN + l) * ED4 + d4];
#pragma unroll
                for (int bs = 0; bs < BPB; bs++) {
                    acc[bs][j].x += sv[bs] * v.x;
                    acc[bs][j].y += sv[bs] * v.y;
                    acc[bs][j].z += sv[bs] * v.z;
                    acc[bs][j].w += sv[bs] * v.w;
                }
            }
        }
    }

    // ---- write: key region (l<4) at 0, value region (l>=4) after ----
    const size_t KEY4 = (size_t)BATCH * (PLEN / 2) * ED4;
#pragma unroll
    for (int j = 0; j < OUT_PER_T; j++) {
        int idx = tid + j * 256;
        int l  = idx / ED4;
        int d4 = idx % ED4;
#pragma unroll
        for (int bs = 0; bs < BPB; bs++) {
            int b = b0 + bs;
            float4* o4;
            if (l < PLEN / 2)
                o4 = (float4*)out + ((size_t)b * (PLEN / 2) + l) * ED4 + d4;
            else
                o4 = (float4*)out + KEY4 +
                     ((size_t)b * (PLEN / 2) + (l - PLEN / 2)) * ED4 + d4;
            *o4 = acc[bs][j];
        }
    }
}

// ---------------------------------------------------------------------------
// Launch — single kernel, everything overlapped.
// Inputs (metadata order): x_querry, x_block, e_a, e_p, idx, task_id
// ---------------------------------------------------------------------------
extern "C" void kernel_launch(void* const* d_in, const int* in_sizes, int n_in,
                              void* d_out, int out_size) {
    const float* x_querry = (const float*)d_in[0];
    const float* x_block  = (const float*)d_in[1];
    const float* e_a      = (const float*)d_in[2];
    const float* e_p      = (const float*)d_in[3];
    const int*   task_id  = (const int*)d_in[5];
    float* out = (float*)d_out;

    size_t xb_float4s = (size_t)in_sizes[1] / 4;
    mega_kernel<<<PMT_BLOCKS + COPY_BLOCKS, 256>>>(
        x_querry, e_a, e_p, x_block, task_id, out, xb_float4s);
}

// round 4
// speedup vs baseline: 1.3083x; 1.3083x over previous
#include <cuda_runtime.h>
#include <math.h>

// Problem constants (fixed by the reference)
#define POOL   100
#define NTASKS 10
#define NB_PT  (POOL / NTASKS)       // 10
#define PLEN   8
#define EMBD   768
#define BATCH  512
#define ED4    (EMBD / 4)            // 192

#define PMT_BLOCKS  BATCH            // 512, one batch row each
#define COPY_BLOCKS 2560
#define OUT_PER_T   ((PLEN * ED4) / 256)   // 6 float4 outputs per thread

// ---------------------------------------------------------------------------
// Single mega kernel, register-capped so the copy path keeps occupancy.
//   blocks [0, PMT_BLOCKS): diag+sim+einsum for ONE batch row (lean regs).
//   blocks [PMT_BLOCKS, ..): streaming copy x_block -> out tail.
// ---------------------------------------------------------------------------
__global__ void __launch_bounds__(256, 6) mega_kernel(
        const float* __restrict__ x_querry,
        const float* __restrict__ e_a,
        const float* __restrict__ e_p,
        const float* __restrict__ x_block,
        const int*   __restrict__ task_id_p,
        float* __restrict__ out,
        size_t xb_float4s) {
    __shared__ float s_diag[NB_PT * EMBD];   // 30 KB
    __shared__ float s_sim[NB_PT];

    if (blockIdx.x >= PMT_BLOCKS) {
        // ================= streaming copy =================
        const float4* src = (const float4*)x_block;
        float4* dst = (float4*)(out + (size_t)BATCH * PLEN * EMBD);

        const size_t stride = (size_t)COPY_BLOCKS * 256;
        size_t i = (size_t)(blockIdx.x - PMT_BLOCKS) * 256 + threadIdx.x;

        for (; i + 7 * stride < xb_float4s; i += 8 * stride) {
            float4 v0 = __ldcs(src + i);
            float4 v1 = __ldcs(src + i + stride);
            float4 v2 = __ldcs(src + i + 2 * stride);
            float4 v3 = __ldcs(src + i + 3 * stride);
            float4 v4 = __ldcs(src + i + 4 * stride);
            float4 v5 = __ldcs(src + i + 5 * stride);
            float4 v6 = __ldcs(src + i + 6 * stride);
            float4 v7 = __ldcs(src + i + 7 * stride);
            __stcs(dst + i,              v0);
            __stcs(dst + i + stride,     v1);
            __stcs(dst + i + 2 * stride, v2);
            __stcs(dst + i + 3 * stride, v3);
            __stcs(dst + i + 4 * stride, v4);
            __stcs(dst + i + 5 * stride, v5);
            __stcs(dst + i + 6 * stride, v6);
            __stcs(dst + i + 7 * stride, v7);
        }
        for (; i < xb_float4s; i += stride)
            __stcs(dst + i, __ldcs(src + i));
        return;
    }

    // ================= pmt path: one batch row =================
    const int task_end = (*task_id_p + 1) * NB_PT;
    const int b = blockIdx.x;
    const int tid = threadIdx.x;
    const int warp = tid >> 5;
    const int lane = tid & 31;

    float4 acc[OUT_PER_T];
#pragma unroll
    for (int j = 0; j < OUT_PER_T; j++)
        acc[j] = make_float4(0.f, 0.f, 0.f, 0.f);

    const float4* ep4 = (const float4*)e_p;

    for (int kc = 0; kc < task_end; kc += NB_PT) {
        const int kn = min(NB_PT, task_end - kc);
        __syncthreads();   // protect s_diag/s_sim reuse across chunks

        // ---- phase A: diag[kk][d] = sum_l e_p[kc+kk, l, d]^2 ----
        for (int i = tid; i < kn * ED4; i += 256) {
            int kk = i / ED4;
            int d4 = i % ED4;
            const float4* p = ep4 + ((size_t)(kc + kk) * PLEN) * ED4 + d4;
            float4 a = make_float4(0.f, 0.f, 0.f, 0.f);
#pragma unroll
            for (int l = 0; l < PLEN; l++) {
                float4 v = p[l * ED4];
                a.x += v.x * v.x; a.y += v.y * v.y;
                a.z += v.z * v.z; a.w += v.w * v.w;
            }
            ((float4*)s_diag)[kk * ED4 + d4] = a;
        }
        __syncthreads();

        // ---- phase B: sims, one warp per k (8 warps cover kn<=10) ----
        for (int kk = warp; kk < kn; kk += 8) {
            int k = kc + kk;
            int row = POOL - task_end + k;

            const float4* xq4 = (const float4*)(x_querry +
                                ((size_t)b * POOL + row) * EMBD);
            const float4* ea4 = (const float4*)(e_a + (size_t)k * EMBD);
            const float4* dg4 = (const float4*)(s_diag + kk * EMBD);

            float s1 = 0.f, s2 = 0.f, s3 = 0.f;
#pragma unroll
            for (int j = 0; j < ED4 / 32; j++) {   // 6 iterations
                int idx = lane + j * 32;
                float4 x = xq4[idx];
                float4 e = ea4[idx];
                float4 g = dg4[idx];
                float a, aa;
                a = x.x * e.x; aa = a * a; s3 += aa; s1 += aa * g.x; s2 += aa * g.x * g.x;
                a = x.y * e.y; aa = a * a; s3 += aa; s1 += aa * g.y; s2 += aa * g.y * g.y;
                a = x.z * e.z; aa = a * a; s3 += aa; s1 += aa * g.z; s2 += aa * g.z * g.z;
                a = x.w * e.w; aa = a * a; s3 += aa; s1 += aa * g.w; s2 += aa * g.w * g.w;
            }
#pragma unroll
            for (int o = 16; o > 0; o >>= 1) {
                s1 += __shfl_down_sync(0xFFFFFFFFu, s1, o);
                s2 += __shfl_down_sync(0xFFFFFFFFu, s2, o);
                s3 += __shfl_down_sync(0xFFFFFFFFu, s3, o);
            }
            if (lane == 0) {
                const float eps = 1e-12f;
                float n1 = fmaxf(sqrtf(s2), eps);
                float n2 = fmaxf(sqrtf(s3), eps);
                s_sim[kk] = s1 / (n1 * n2);
            }
        }
        __syncthreads();

        // ---- phase C: accumulate einsum ----
        for (int kk = 0; kk < kn; kk++) {
            float s = s_sim[kk];
#pragma unroll
            for (int j = 0; j < OUT_PER_T; j++) {
                int idx = tid + j * 256;
                int l  = idx / ED4;
                int d4 = idx % ED4;
                float4 v = ep4[((size_t)(kc + kk) * PLEN + l) * ED4 + d4];
                acc[j].x += s * v.x;
                acc[j].y += s * v.y;
                acc[j].z += s * v.z;
                acc[j].w += s * v.w;
            }
        }
    }

    // ---- write: key region (l<4) at 0, value region (l>=4) after ----
    const size_t KEY4 = (size_t)BATCH * (PLEN / 2) * ED4;
#pragma unroll
    for (int j = 0; j < OUT_PER_T; j++) {
        int idx = tid + j * 256;
        int l  = idx / ED4;
        int d4 = idx % ED4;
        float4* o4;
        if (l < PLEN / 2)
            o4 = (float4*)out + ((size_t)b * (PLEN / 2) + l) * ED4 + d4;
        else
            o4 = (float4*)out + KEY4 +
                 ((size_t)b * (PLEN / 2) + (l - PLEN / 2)) * ED4 + d4;
        *o4 = acc[j];
    }
}

// ---------------------------------------------------------------------------
// Launch — single kernel, everything overlapped.
// Inputs (metadata order): x_querry, x_block, e_a, e_p, idx, task_id
// ---------------------------------------------------------------------------
extern "C" void kernel_launch(void* const* d_in, const int* in_sizes, int n_in,
                              void* d_out, int out_size) {
    const float* x_querry = (const float*)d_in[0];
    const float* x_block  = (const float*)d_in[1];
    const float* e_a      = (const float*)d_in[2];
    const float* e_p      = (const float*)d_in[3];
    const int*   task_id  = (const int*)d_in[5];
    float* out = (float*)d_out;

    size_t xb_float4s = (size_t)in_sizes[1] / 4;
    mega_kernel<<<PMT_BLOCKS + COPY_BLOCKS, 256>>>(
        x_querry, e_a, e_p, x_block, task_id, out, xb_float4s);
}

// round 5
// speedup vs baseline: 1.4108x; 1.0784x over previous
#include <cuda_runtime.h>
#include <math.h>

// Problem constants (fixed by the reference)
#define POOL   100
#define NTASKS 10
#define NB_PT  (POOL / NTASKS)       // 10
#define PLEN   8
#define EMBD   768
#define BATCH  512
#define ED4    (EMBD / 4)            // 192

#define BG          8                // batch rows per sim block (one warp each)
#define COPY_BLOCKS 2560             // copy blocks come FIRST in mega
#define PMT_BLOCKS  BATCH            // pmt blocks come LAST

// Scratch (allocation-free per harness rules)
__device__ float g_sim[BATCH * POOL];

// ---------------------------------------------------------------------------
// Kernel 1 (PRIMARY, fused diag + sim):
//   grid = (BATCH/BG, POOL); block = 256 = 8 warps.
//   Triggers dependent launch immediately so the mega kernel's copy blocks
//   start flooding SMs while sim is still running.
// ---------------------------------------------------------------------------
__global__ void sim_fused_kernel(const float* __restrict__ x_querry,
                                 const float* __restrict__ e_a,
                                 const float* __restrict__ e_p,
                                 const int*   __restrict__ task_id_p) {
    asm volatile("griddepcontrol.launch_dependents;");

    const int task_end = (*task_id_p + 1) * NB_PT;
    const int k = blockIdx.y;
    if (k >= task_end) return;

    __shared__ float s_diag[EMBD];
    __shared__ float s_ea[EMBD];

    // Phase 1: diag + ea into smem (256 threads over 768 elems)
    const float* epk = e_p + (size_t)k * PLEN * EMBD;
    for (int d = threadIdx.x; d < EMBD; d += 256) {
        float acc = 0.f;
#pragma unroll
        for (int l = 0; l < PLEN; l++) {
            float v = epk[l * EMBD + d];
            acc += v * v;
        }
        s_diag[d] = acc;
        s_ea[d]   = e_a[(size_t)k * EMBD + d];
    }
    __syncthreads();

    // Phase 2: one warp per batch row
    const int warp = threadIdx.x >> 5;
    const int lane = threadIdx.x & 31;
    const int b = blockIdx.x * BG + warp;
    const int row = POOL - task_end + k;

    const float4* xq4 = (const float4*)(x_querry + ((size_t)b * POOL + row) * EMBD);
    const float4* ea4 = (const float4*)s_ea;
    const float4* dg4 = (const float4*)s_diag;

    float s1 = 0.f, s2 = 0.f, s3 = 0.f;
#pragma unroll
    for (int j = 0; j < ED4 / 32; j++) {   // 6 iterations
        int idx = lane + j * 32;
        float4 x = xq4[idx];
        float4 e = ea4[idx];
        float4 g = dg4[idx];
        float a, aa;
        a = x.x * e.x; aa = a * a; s3 += aa; s1 += aa * g.x; s2 += aa * g.x * g.x;
        a = x.y * e.y; aa = a * a; s3 += aa; s1 += aa * g.y; s2 += aa * g.y * g.y;
        a = x.z * e.z; aa = a * a; s3 += aa; s1 += aa * g.z; s2 += aa * g.z * g.z;
        a = x.w * e.w; aa = a * a; s3 += aa; s1 += aa * g.w; s2 += aa * g.w * g.w;
    }
#pragma unroll
    for (int o = 16; o > 0; o >>= 1) {
        s1 += __shfl_down_sync(0xFFFFFFFFu, s1, o);
        s2 += __shfl_down_sync(0xFFFFFFFFu, s2, o);
        s3 += __shfl_down_sync(0xFFFFFFFFu, s3, o);
    }
    if (lane == 0) {
        const float eps = 1e-12f;
        float n1 = fmaxf(sqrtf(s2), eps);
        float n2 = fmaxf(sqrtf(s3), eps);
        g_sim[(size_t)b * POOL + k] = s1 / (n1 * n2);
    }
}

// ---------------------------------------------------------------------------
// Kernel 2 (SECONDARY, mega): copy blocks FIRST (no dependency, start under
// PDL while sim still runs); pmt blocks LAST (griddepcontrol.wait before
// reading g_sim — satisfied long before they get scheduled).
// ---------------------------------------------------------------------------
__global__ void __launch_bounds__(256) mega_kernel(
        const float* __restrict__ e_p,
        const float* __restrict__ x_block,
        const int*   __restrict__ task_id_p,
        float* __restrict__ out,
        size_t xb_float4s) {
    if (blockIdx.x < COPY_BLOCKS) {
        // ---- streaming copy: x_block -> out tail ----
        const float4* src = (const float4*)x_block;
        float4* dst = (float4*)(out + (size_t)BATCH * PLEN * EMBD);

        const size_t stride = (size_t)COPY_BLOCKS * 256;
        size_t i = (size_t)blockIdx.x * 256 + threadIdx.x;

        for (; i + 7 * stride < xb_float4s; i += 8 * stride) {
            float4 v0 = __ldcs(src + i);
            float4 v1 = __ldcs(src + i + stride);
            float4 v2 = __ldcs(src + i + 2 * stride);
            float4 v3 = __ldcs(src + i + 3 * stride);
            float4 v4 = __ldcs(src + i + 4 * stride);
            float4 v5 = __ldcs(src + i + 5 * stride);
            float4 v6 = __ldcs(src + i + 6 * stride);
            float4 v7 = __ldcs(src + i + 7 * stride);
            __stcs(dst + i,              v0);
            __stcs(dst + i + stride,     v1);
            __stcs(dst + i + 2 * stride, v2);
            __stcs(dst + i + 3 * stride, v3);
            __stcs(dst + i + 4 * stride, v4);
            __stcs(dst + i + 5 * stride, v5);
            __stcs(dst + i + 6 * stride, v6);
            __stcs(dst + i + 7 * stride, v7);
        }
        for (; i < xb_float4s; i += stride)
            __stcs(dst + i, __ldcs(src + i));
        return;
    }

    // ---- pmt: int_pmt[b,l,d] = sum_k sim[b,k] * e_p[k,l,d] ----
    asm volatile("griddepcontrol.wait;" ::: "memory");

    const int task_end = (*task_id_p + 1) * NB_PT;
    const int b = blockIdx.x - COPY_BLOCKS;

    __shared__ float s_sim[POOL];
    if (threadIdx.x < POOL)
        s_sim[threadIdx.x] = g_sim[(size_t)b * POOL + threadIdx.x];
    __syncthreads();

    const float4* ep4 = (const float4*)e_p;
    const size_t KEY4 = (size_t)BATCH * (PLEN / 2) * ED4;

    // PLEN*ED4 = 1536 float4 outputs per b; 256 threads -> 6 each
    for (int idx = threadIdx.x; idx < PLEN * ED4; idx += 256) {
        int l  = idx / ED4;
        int d4 = idx % ED4;
        float4 acc = make_float4(0.f, 0.f, 0.f, 0.f);
        for (int kk = 0; kk < task_end; kk++) {
            float s  = s_sim[kk];
            float4 v = ep4[((size_t)kk * PLEN + l) * ED4 + d4];
            acc.x += s * v.x; acc.y += s * v.y;
            acc.z += s * v.z; acc.w += s * v.w;
        }
        float4* o4;
        if (l < PLEN / 2)
            o4 = (float4*)out + ((size_t)b * (PLEN / 2) + l) * ED4 + d4;
        else
            o4 = (float4*)out + KEY4 +
                 ((size_t)b * (PLEN / 2) + (l - PLEN / 2)) * ED4 + d4;
        *o4 = acc;
    }
}

// ---------------------------------------------------------------------------
// Launch: sim (primary), then mega (secondary) with PDL so its copy blocks
// start before sim completes.
// Inputs (metadata order): x_querry, x_block, e_a, e_p, idx, task_id
// ---------------------------------------------------------------------------
extern "C" void kernel_launch(void* const* d_in, const int* in_sizes, int n_in,
                              void* d_out, int out_size) {
    const float* x_querry = (const float*)d_in[0];
    const float* x_block  = (const float*)d_in[1];
    const float* e_a      = (const float*)d_in[2];
    const float* e_p      = (const float*)d_in[3];
    const int*   task_id  = (const int*)d_in[5];
    float* out = (float*)d_out;

    // Primary: fused diag+sim
    dim3 sim_grid(BATCH / BG, POOL);
    sim_fused_kernel<<<sim_grid, 256>>>(x_querry, e_a, e_p, task_id);

    // Secondary: mega (copy + pmt) with programmatic dependent launch
    size_t xb_float4s = (size_t)in_sizes[1] / 4;

    cudaLaunchConfig_t cfg = {};
    cfg.gridDim  = dim3(COPY_BLOCKS + PMT_BLOCKS);
    cfg.blockDim = dim3(256);
    cfg.dynamicSmemBytes = 0;
    cfg.stream = 0;   // legacy default stream (same one the harness captures)

    cudaLaunchAttribute attr[1];
    attr[0].id = cudaLaunchAttributeProgrammaticStreamSerialization;
    attr[0].val.programmaticStreamSerializationAllowed = 1;
    cfg.attrs = attr;
    cfg.numAttrs = 1;

    cudaLaunchKernelEx(&cfg, mega_kernel, e_p, x_block, task_id, out,
                       xb_float4s);
}